// round 1
// baseline (speedup 1.0000x reference)
#include <cuda_runtime.h>
#include <cstdint>

#define T_STEPS 1024
#define B_SZ    32
#define I_SZ    512
#define H_SZ    512
#define G4      2048                 // 4*H
#define TBH     (T_STEPS * B_SZ * H_SZ)
#define BH      (B_SZ * H_SZ)
#define NCTA    128

typedef unsigned long long ull;

// ---------------- device scratch (no allocation allowed) ----------------
__device__ float g_gates[(size_t)T_STEPS * B_SZ * G4];   // [t][b][p]  256 MB
__device__ float g_wih_p[G4 * I_SZ];                     // packed W_ih (p = 4j+g)
__device__ float g_whh_p[G4 * H_SZ];                     // packed W_hh
__device__ float g_bias_p[G4];                           // b_ih + b_hh, packed
__device__ float g_hbuf[2 * BH];                         // ping-pong h broadcast
__device__ unsigned g_bar_leaf[8];
__device__ unsigned g_bar_root;
__device__ volatile unsigned g_bar_gen;

// ---------------- packed f32x2 helpers ----------------
__device__ __forceinline__ void ffma2(ull &d, ull a, ull b) {
    asm("fma.rn.f32x2 %0, %1, %2, %3;" : "=l"(d) : "l"(a), "l"(b), "l"(d));
}
__device__ __forceinline__ ull pack2(float x) {
    ull r; asm("mov.b64 %0, {%1, %1};" : "=l"(r) : "f"(x)); return r;
}
__device__ __forceinline__ float2 unpack2(ull v) {
    float2 r; asm("mov.b64 {%0, %1}, %2;" : "=f"(r.x), "=f"(r.y) : "l"(v)); return r;
}

__device__ __forceinline__ float sigf(float x) {
    return __fdividef(1.f, 1.f + __expf(-x));
}
__device__ __forceinline__ float tanh_fast(float x) {
    float ax = fabsf(x);
    float e  = __expf(-2.f * ax);
    float r  = __fdividef(1.f - e, 1.f + e);
    return copysignf(r, x);
}

// ---------------- grid barrier (two-level, reset-free via atomicSub) ----------------
__device__ __forceinline__ void grid_barrier() {
    __syncthreads();
    if (threadIdx.x == 0) {
        __threadfence();
        unsigned gen  = g_bar_gen;               // read BEFORE arriving
        unsigned leaf = blockIdx.x & 7u;         // 8 leaves x 16 CTAs
        if (atomicAdd(&g_bar_leaf[leaf], 1u) == 15u) {
            atomicSub(&g_bar_leaf[leaf], 16u);   // commutative reset (order-safe)
            if (atomicAdd(&g_bar_root, 1u) == 7u) {
                atomicSub(&g_bar_root, 8u);
                __threadfence();
                atomicAdd((unsigned*)&g_bar_gen, 1u);
            } else {
                while (g_bar_gen == gen) __nanosleep(64);
            }
        } else {
            while (g_bar_gen == gen) __nanosleep(64);
        }
        __threadfence();
    }
    __syncthreads();
}

// ---------------- prep: pack weights/bias into p = 4j + gate order ----------------
__global__ void prep_kernel(const float* __restrict__ Wih, const float* __restrict__ Whh,
                            const float* __restrict__ bih, const float* __restrict__ bhh,
                            const float* __restrict__ h0) {
    int p    = blockIdx.x;
    int orig = (p & 3) * H_SZ + (p >> 2);        // gate*H + j
    const float* srcI = Wih + (size_t)orig * I_SZ;
    const float* srcH = Whh + (size_t)orig * H_SZ;
    float* dI = g_wih_p + (size_t)p * I_SZ;
    float* dH = g_whh_p + (size_t)p * H_SZ;
    for (int k = threadIdx.x; k < I_SZ; k += blockDim.x) dI[k] = srcI[k];
    for (int k = threadIdx.x; k < H_SZ; k += blockDim.x) dH[k] = srcH[k];
    if (threadIdx.x == 0) g_bias_p[p] = bih[orig] + bhh[orig];
    if (p < B_SZ) {
        for (int k = threadIdx.x; k < H_SZ; k += blockDim.x)
            g_hbuf[p * H_SZ + k] = h0[p * H_SZ + k];
    }
}

// ---------------- phase 1: gates_x GEMM  C[m][p] = A[m][:] . Wp[p][:] + bias[p] ----------------
#define BM 128
#define BN 64
#define BK 16
#define LDA (BM + 4)   // 132 (16B-aligned rows)
#define LDB (BN + 4)   // 68

__global__ __launch_bounds__(256) void gemm_x_kernel(const float* __restrict__ A) {
    __shared__ float sA[BK][LDA];
    __shared__ float sB[BK][LDB];
    int tid   = threadIdx.x;
    int mBase = blockIdx.y * BM;
    int nBase = blockIdx.x * BN;
    int tm = tid & 15, tn = tid >> 4;   // 16x16 threads -> 8x4 outputs each

    int aM0 = tid >> 2;                 // 0..63
    int aK0 = (tid & 3) * 4;            // 0,4,8,12
    int bN  = tid >> 2;                 // 0..63
    int bK  = (tid & 3) * 4;

    const float* Ag = A + (size_t)mBase * I_SZ;
    const float* Bg = g_wih_p + (size_t)nBase * I_SZ;

    float4 ra0 = *(const float4*)(Ag + (size_t)aM0 * I_SZ + aK0);
    float4 ra1 = *(const float4*)(Ag + (size_t)(aM0 + 64) * I_SZ + aK0);
    float4 rb  = *(const float4*)(Bg + (size_t)bN * I_SZ + bK);

    ull acc[4][4];
#pragma unroll
    for (int u = 0; u < 4; u++)
#pragma unroll
        for (int j = 0; j < 4; j++) acc[u][j] = 0ull;

    const int KT = I_SZ / BK;
    for (int kt = 0; kt < KT; kt++) {
        sA[aK0 + 0][aM0] = ra0.x; sA[aK0 + 1][aM0] = ra0.y;
        sA[aK0 + 2][aM0] = ra0.z; sA[aK0 + 3][aM0] = ra0.w;
        sA[aK0 + 0][aM0 + 64] = ra1.x; sA[aK0 + 1][aM0 + 64] = ra1.y;
        sA[aK0 + 2][aM0 + 64] = ra1.z; sA[aK0 + 3][aM0 + 64] = ra1.w;
        sB[bK + 0][bN] = rb.x; sB[bK + 1][bN] = rb.y;
        sB[bK + 2][bN] = rb.z; sB[bK + 3][bN] = rb.w;
        __syncthreads();

        if (kt + 1 < KT) {                       // register prefetch of next tile
            int k0 = (kt + 1) * BK;
            ra0 = *(const float4*)(Ag + (size_t)aM0 * I_SZ + k0 + aK0);
            ra1 = *(const float4*)(Ag + (size_t)(aM0 + 64) * I_SZ + k0 + aK0);
            rb  = *(const float4*)(Bg + (size_t)bN * I_SZ + k0 + bK);
        }

#pragma unroll
        for (int kk = 0; kk < BK; kk++) {
            ulonglong2 a01 = *(const ulonglong2*)&sA[kk][tm * 8];
            ulonglong2 a23 = *(const ulonglong2*)&sA[kk][tm * 8 + 4];
            float4 b4 = *(const float4*)&sB[kk][tn * 4];
            ull b0 = pack2(b4.x), b1 = pack2(b4.y), b2 = pack2(b4.z), b3 = pack2(b4.w);
            ffma2(acc[0][0], a01.x, b0); ffma2(acc[0][1], a01.x, b1);
            ffma2(acc[0][2], a01.x, b2); ffma2(acc[0][3], a01.x, b3);
            ffma2(acc[1][0], a01.y, b0); ffma2(acc[1][1], a01.y, b1);
            ffma2(acc[1][2], a01.y, b2); ffma2(acc[1][3], a01.y, b3);
            ffma2(acc[2][0], a23.x, b0); ffma2(acc[2][1], a23.x, b1);
            ffma2(acc[2][2], a23.x, b2); ffma2(acc[2][3], a23.x, b3);
            ffma2(acc[3][0], a23.y, b0); ffma2(acc[3][1], a23.y, b1);
            ffma2(acc[3][2], a23.y, b2); ffma2(acc[3][3], a23.y, b3);
        }
        __syncthreads();
    }

    float4 bias = *(const float4*)&g_bias_p[nBase + tn * 4];
    float* C = g_gates + (size_t)(mBase + tm * 8) * G4 + nBase + tn * 4;
#pragma unroll
    for (int u = 0; u < 4; u++) {
        float2 c0 = unpack2(acc[u][0]);
        float2 c1 = unpack2(acc[u][1]);
        float2 c2 = unpack2(acc[u][2]);
        float2 c3 = unpack2(acc[u][3]);
        float4 lo = {c0.x + bias.x, c1.x + bias.y, c2.x + bias.z, c3.x + bias.w};
        float4 hi = {c0.y + bias.x, c1.y + bias.y, c2.y + bias.z, c3.y + bias.w};
        *(float4*)(C + (size_t)(2 * u) * G4)     = lo;
        *(float4*)(C + (size_t)(2 * u + 1) * G4) = hi;
    }
}

// ---------------- phase 2: persistent recurrent scan ----------------
// 128 CTAs; CTA c owns h columns j in [4c, 4c+4)  (packed gate rows [16c, 16c+16)).
// 256 threads: tid = kh*128 + r; r = b*4 + jl; thread computes all 4 gates of (b, j)
// over half the K range; halves combined via SMEM.
__global__ __launch_bounds__(256) void scan_kernel(const float* __restrict__ c0,
                                                   float* __restrict__ out, int out_size) {
    extern __shared__ float smem[];
    float* sh_w    = smem;                    // 16*512  = 8192 floats (W_hh slice, resident)
    float* sh_h    = smem + 16 * H_SZ;        // 32*512  = 16384 floats
    float* sh_part = sh_h + BH;               // 512 floats (K-split partials)

    int tid = threadIdx.x;
    int cta = blockIdx.x;
    int kh  = tid >> 7;        // K-half
    int r   = tid & 127;
    int b   = r >> 2;
    int jl  = r & 3;
    int j   = cta * 4 + jl;

    // W_hh slice -> SMEM once (reused 1024 steps)
    {
        const float* src = g_whh_p + (size_t)cta * 16 * H_SZ;
        for (int i = tid * 4; i < 16 * H_SZ; i += 256 * 4)
            *(float4*)(sh_w + i) = *(const float4*)(src + i);
    }
    float c_val = (kh == 0) ? c0[b * H_SZ + j] : 0.f;

    const float* gx_base = g_gates + (size_t)b * G4 + cta * 16 + jl * 4;
    const float* wbase   = sh_w + (jl * 4) * H_SZ + kh * 256;

    for (int t = 0; t < T_STEPS; t++) {
        // broadcast h (L1 may be stale within launch -> .cg)
        const float4* hsrc = (const float4*)(g_hbuf + (t & 1) * BH);
#pragma unroll
        for (int i = tid; i < BH / 4; i += 256)
            ((float4*)sh_h)[i] = __ldcg(hsrc + i);
        __syncthreads();

        float4 gxv = make_float4(0.f, 0.f, 0.f, 0.f);
        if (kh == 0) gxv = __ldg((const float4*)(gx_base + (size_t)t * B_SZ * G4));

        ull acc[4][2] = {};
        const ulonglong2* h2 = (const ulonglong2*)(sh_h + b * H_SZ) + kh * 64;
#pragma unroll 4
        for (int kv = 0; kv < 64; kv++) {
            ulonglong2 hv = h2[kv];
#pragma unroll
            for (int g = 0; g < 4; g++) {
                ulonglong2 wv = ((const ulonglong2*)(wbase + g * H_SZ))[kv];
                ffma2(acc[g][0], hv.x, wv.x);
                ffma2(acc[g][1], hv.y, wv.y);
            }
        }
        float p[4];
#pragma unroll
        for (int g = 0; g < 4; g++) {
            float2 e = unpack2(acc[g][0]);
            float2 f = unpack2(acc[g][1]);
            p[g] = (e.x + e.y) + (f.x + f.y);
        }
        if (kh == 1)
            ((float4*)sh_part)[r] = make_float4(p[0], p[1], p[2], p[3]);
        __syncthreads();

        if (kh == 0) {
            float4 q = ((float4*)sh_part)[r];
            float pi = p[0] + q.x + gxv.x;
            float pf = p[1] + q.y + gxv.y;
            float pg = p[2] + q.z + gxv.z;
            float po = p[3] + q.w + gxv.w;
            float ig = sigf(pi), fg = sigf(pf), og = sigf(po);
            float gg = tanh_fast(pg);
            c_val = fg * c_val + ig * gg;
            float h_new = og * tanh_fast(c_val);
            g_hbuf[((t + 1) & 1) * BH + b * H_SZ + j] = h_new;
            out[(size_t)t * BH + b * H_SZ + j] = h_new;
            if (t == T_STEPS - 1 && out_size >= TBH + 2 * BH) {
                out[TBH + b * H_SZ + j]      = h_new;   // h_f
                out[TBH + BH + b * H_SZ + j] = c_val;   // c_f
            }
        }
        grid_barrier();
    }
}

// ---------------- launch ----------------
extern "C" void kernel_launch(void* const* d_in, const int* in_sizes, int n_in,
                              void* d_out, int out_size) {
    const float* input = (const float*)d_in[0];
    const float* h0    = (const float*)d_in[1];
    const float* c0    = (const float*)d_in[2];
    const float* Wih   = (const float*)d_in[3];
    const float* Whh   = (const float*)d_in[4];
    const float* bih   = (const float*)d_in[5];
    const float* bhh   = (const float*)d_in[6];
    float* out = (float*)d_out;

    prep_kernel<<<G4, 128>>>(Wih, Whh, bih, bhh, h0);

    dim3 grid(G4 / BN, (T_STEPS * B_SZ) / BM);
    gemm_x_kernel<<<grid, 256>>>(input);

    const int scan_smem = (16 * H_SZ + BH + 512) * (int)sizeof(float);  // 100352 B
    cudaFuncSetAttribute(scan_kernel, cudaFuncAttributeMaxDynamicSharedMemorySize, scan_smem);
    scan_kernel<<<NCTA, 256, scan_smem>>>(c0, out, out_size);
}

// round 2
// speedup vs baseline: 3.6232x; 3.6232x over previous
#include <cuda_runtime.h>
#include <cstdint>

#define T_STEPS 1024
#define B_SZ    32
#define I_SZ    512
#define H_SZ    512
#define G4      2048                 // 4*H
#define TBH     (T_STEPS * B_SZ * H_SZ)
#define BH      (B_SZ * H_SZ)
#define NG      4                    // independent batch groups
#define NC      32                   // CTAs per group

typedef unsigned long long ull;

// ---------------- device scratch (no allocation allowed) ----------------
__device__ float g_gates[(size_t)T_STEPS * B_SZ * G4];   // [t][b][p], p = 4j+g
__device__ float g_wih_p[G4 * I_SZ];                     // packed W_ih (p = 4j+g)
__device__ float g_whh_sw[NC * 64 * H_SZ];               // per-CTA swizzled W_hh (LDS-order)
__device__ float g_bias_p[G4];                           // b_ih + b_hh, packed
__device__ float g_hbufT[NG * 2 * 8 * H_SZ];             // [grp][phase][j][b8] transposed h
__device__ unsigned g_cnt[NG * 32];                      // per-group arrival counters (padded)
__device__ unsigned g_gen2[NG * 32];                     // per-group generation (padded)

// ---------------- packed f32x2 helpers ----------------
__device__ __forceinline__ void ffma2(ull &d, ull a, ull b) {
    asm("fma.rn.f32x2 %0, %1, %2, %3;" : "=l"(d) : "l"(a), "l"(b), "l"(d));
}
__device__ __forceinline__ void fadd2(ull &d, ull a) {
    asm("add.rn.f32x2 %0, %1, %2;" : "=l"(d) : "l"(d), "l"(a));
}
__device__ __forceinline__ ull pack2(float x) {
    ull r; asm("mov.b64 %0, {%1, %1};" : "=l"(r) : "f"(x)); return r;
}
__device__ __forceinline__ float2 unpack2(ull v) {
    float2 r; asm("mov.b64 {%0, %1}, %2;" : "=f"(r.x), "=f"(r.y) : "l"(v)); return r;
}
__device__ __forceinline__ unsigned ld_acq(const unsigned* p) {
    unsigned v; asm volatile("ld.acquire.gpu.global.u32 %0, [%1];" : "=r"(v) : "l"(p) : "memory");
    return v;
}
__device__ __forceinline__ void st_rel(unsigned* p, unsigned v) {
    asm volatile("st.release.gpu.global.u32 [%0], %1;" :: "l"(p), "r"(v) : "memory");
}

__device__ __forceinline__ float sigf(float x) {
    return __fdividef(1.f, 1.f + __expf(-x));
}
__device__ __forceinline__ float tanh_fast(float x) {
    float ax = fabsf(x);
    float e  = __expf(-2.f * ax);
    float r  = __fdividef(1.f - e, 1.f + e);
    return copysignf(r, x);
}

// ---------------- prep: pack/swizzle weights, transpose h0, reset barriers ----------------
__global__ void prep_kernel(const float* __restrict__ Wih, const float* __restrict__ Whh,
                            const float* __restrict__ bih, const float* __restrict__ bhh,
                            const float* __restrict__ h0) {
    int p = blockIdx.x;                     // packed row p = 4j + g
    int g = p & 3, j = p >> 2;
    int orig = g * H_SZ + j;

    const float* srcI = Wih + (size_t)orig * I_SZ;
    float* dI = g_wih_p + (size_t)p * I_SZ;
    for (int k = threadIdx.x; k < I_SZ; k += blockDim.x) dI[k] = srcI[k];

    // W_hh swizzled into the scan's exact per-thread LDS.128 order:
    // CTA c owns rows [64c, 64c+64); thread tv = kq*32+rg reads rows (2rg, 2rg+1)
    // over K-range kq*64..kq*64+63; i-th float4 of the thread at float (i*256+tv)*4.
    const float* srcH = Whh + (size_t)orig * H_SZ;
    int cc = p >> 6, idx = p & 63, rg = idx >> 1, r = idx & 1;
    float* base = g_whh_sw + (size_t)cc * (64 * H_SZ);
    for (int k = threadIdx.x; k < H_SZ; k += blockDim.x) {
        int kq = k >> 6, rem = k & 63, kb = rem >> 2, ko = k & 3;
        int i  = kb * 2 + r, tv = kq * 32 + rg;
        base[(size_t)(i * 256 + tv) * 4 + ko] = srcH[k];
    }
    if (threadIdx.x == 0) g_bias_p[p] = bih[orig] + bhh[orig];

    if (p < H_SZ) {                          // transpose h0 -> [grp][0][j=p][b8]
        for (int b = threadIdx.x; b < B_SZ; b += blockDim.x)
            g_hbufT[(size_t)(b >> 3) * 2 * 8 * H_SZ + p * 8 + (b & 7)] = h0[(size_t)b * H_SZ + p];
    }
    if (p < NG && threadIdx.x == 0) { g_cnt[p * 32] = 0; g_gen2[p * 32] = 0; }
}

// ---------------- phase 1: gates_x GEMM  C[m][p] = A[m][:] . Wp[p][:] + bias[p] ----------------
#define BM 128
#define BN 64
#define BK 16
#define LDA (BM + 4)
#define LDB (BN + 4)

__global__ __launch_bounds__(256) void gemm_x_kernel(const float* __restrict__ A) {
    __shared__ float sA[BK][LDA];
    __shared__ float sB[BK][LDB];
    int tid   = threadIdx.x;
    int mBase = blockIdx.y * BM;
    int nBase = blockIdx.x * BN;
    int tm = tid & 15, tn = tid >> 4;

    int aM0 = tid >> 2;
    int aK0 = (tid & 3) * 4;
    int bN  = tid >> 2;
    int bK  = (tid & 3) * 4;

    const float* Ag = A + (size_t)mBase * I_SZ;
    const float* Bg = g_wih_p + (size_t)nBase * I_SZ;

    float4 ra0 = *(const float4*)(Ag + (size_t)aM0 * I_SZ + aK0);
    float4 ra1 = *(const float4*)(Ag + (size_t)(aM0 + 64) * I_SZ + aK0);
    float4 rb  = *(const float4*)(Bg + (size_t)bN * I_SZ + bK);

    ull acc[4][4];
#pragma unroll
    for (int u = 0; u < 4; u++)
#pragma unroll
        for (int j = 0; j < 4; j++) acc[u][j] = 0ull;

    const int KT = I_SZ / BK;
    for (int kt = 0; kt < KT; kt++) {
        sA[aK0 + 0][aM0] = ra0.x; sA[aK0 + 1][aM0] = ra0.y;
        sA[aK0 + 2][aM0] = ra0.z; sA[aK0 + 3][aM0] = ra0.w;
        sA[aK0 + 0][aM0 + 64] = ra1.x; sA[aK0 + 1][aM0 + 64] = ra1.y;
        sA[aK0 + 2][aM0 + 64] = ra1.z; sA[aK0 + 3][aM0 + 64] = ra1.w;
        sB[bK + 0][bN] = rb.x; sB[bK + 1][bN] = rb.y;
        sB[bK + 2][bN] = rb.z; sB[bK + 3][bN] = rb.w;
        __syncthreads();

        if (kt + 1 < KT) {
            int k0 = (kt + 1) * BK;
            ra0 = *(const float4*)(Ag + (size_t)aM0 * I_SZ + k0 + aK0);
            ra1 = *(const float4*)(Ag + (size_t)(aM0 + 64) * I_SZ + k0 + aK0);
            rb  = *(const float4*)(Bg + (size_t)bN * I_SZ + k0 + bK);
        }

#pragma unroll
        for (int kk = 0; kk < BK; kk++) {
            ulonglong2 a01 = *(const ulonglong2*)&sA[kk][tm * 8];
            ulonglong2 a23 = *(const ulonglong2*)&sA[kk][tm * 8 + 4];
            float4 b4 = *(const float4*)&sB[kk][tn * 4];
            ull b0 = pack2(b4.x), b1 = pack2(b4.y), b2 = pack2(b4.z), b3 = pack2(b4.w);
            ffma2(acc[0][0], a01.x, b0); ffma2(acc[0][1], a01.x, b1);
            ffma2(acc[0][2], a01.x, b2); ffma2(acc[0][3], a01.x, b3);
            ffma2(acc[1][0], a01.y, b0); ffma2(acc[1][1], a01.y, b1);
            ffma2(acc[1][2], a01.y, b2); ffma2(acc[1][3], a01.y, b3);
            ffma2(acc[2][0], a23.x, b0); ffma2(acc[2][1], a23.x, b1);
            ffma2(acc[2][2], a23.x, b2); ffma2(acc[2][3], a23.x, b3);
            ffma2(acc[3][0], a23.y, b0); ffma2(acc[3][1], a23.y, b1);
            ffma2(acc[3][2], a23.y, b2); ffma2(acc[3][3], a23.y, b3);
        }
        __syncthreads();
    }

    float4 bias = *(const float4*)&g_bias_p[nBase + tn * 4];
    float* C = g_gates + (size_t)(mBase + tm * 8) * G4 + nBase + tn * 4;
#pragma unroll
    for (int u = 0; u < 4; u++) {
        float2 c0 = unpack2(acc[u][0]);
        float2 c1 = unpack2(acc[u][1]);
        float2 c2 = unpack2(acc[u][2]);
        float2 c3 = unpack2(acc[u][3]);
        float4 lo = {c0.x + bias.x, c1.x + bias.y, c2.x + bias.z, c3.x + bias.w};
        float4 hi = {c0.y + bias.x, c1.y + bias.y, c2.y + bias.z, c3.y + bias.w};
        *(float4*)(C + (size_t)(2 * u) * G4)     = lo;
        *(float4*)(C + (size_t)(2 * u + 1) * G4) = hi;
    }
}

// ---------------- phase 2: persistent recurrent scan ----------------
// 4 independent groups x 32 CTAs. Group grp owns batches [8*grp, 8*grp+8).
// CTA c owns packed rows [64c, 64c+64) (j in [16c, 16c+16)).
// Thread tid: rg = tid&31 (row pair 2rg,2rg+1), kq = tid>>5 (K-eighth of 64 k).
// Accumulates 8 batches as 4 packed f32x2 per row. h stored transposed [j][b8].
__global__ __launch_bounds__(256) void scan_kernel(const float* __restrict__ c0,
                                                   float* __restrict__ out, int out_size) {
    extern __shared__ float smem[];
    float* sh_w    = smem;                             // 32768 floats (128 KB)
    float* sh_h    = smem + 32768;                     // 4096 floats  (16 KB) [k][b8]
    ull*   sh_part = (ull*)(smem + 32768 + 4096);      // 256*9 ull (18 KB)
    float* sh_gate = smem + 32768 + 4096 + 4608;       // 64 rows * 10 floats (2.5 KB)

    int tid = threadIdx.x;
    int grp = blockIdx.x >> 5;
    int c   = blockIdx.x & 31;
    int rg = tid & 31, kq = tid >> 5;

    // W_hh slice (pre-swizzled, conflict-free) -> SMEM once
    {
        const float4* wsrc = (const float4*)(g_whh_sw + (size_t)c * (64 * H_SZ));
        float4* wdst = (float4*)sh_w;
#pragma unroll
        for (int i = 0; i < 32; i++) wdst[tid + i * 256] = __ldg(wsrc + tid + i * 256);
    }

    int b8 = tid >> 4, jl = tid & 15;            // epilogue mapping (tid < 128)
    float c_val = 0.f;
    const float* gxp = g_gates;
    if (tid < 128) {
        c_val = c0[(size_t)(grp * 8 + b8) * H_SZ + c * 16 + jl];
        gxp   = g_gates + (size_t)(grp * 8 + b8) * G4 + c * 64 + jl * 4;
    }
    unsigned* cnt = &g_cnt[grp * 32];
    unsigned* gen = &g_gen2[grp * 32];
    float* hT0 = g_hbufT + (size_t)grp * 2 * 8 * H_SZ;

    for (int t = 0; t < T_STEPS; t++) {
        float4 gxv = make_float4(0.f, 0.f, 0.f, 0.f);
        if (tid < 128) gxv = __ldg((const float4*)(gxp + (size_t)t * (B_SZ * G4)));

        // h[t] (already transposed) -> SMEM; .cg: L2 is the coherence point
        {
            const float4* hsrc = (const float4*)(hT0 + (t & 1) * (8 * H_SZ));
            float4* hdst = (float4*)sh_h;
#pragma unroll
            for (int i = 0; i < 4; i++) hdst[tid + i * 256] = __ldcg(hsrc + tid + i * 256);
        }
        __syncthreads();

        ull acc[8];
#pragma unroll
        for (int i = 0; i < 8; i++) acc[i] = 0ull;

        const float4* wv = ((const float4*)sh_w) + tid;
        const ulonglong2* hv = ((const ulonglong2*)sh_h) + (kq << 7);
#pragma unroll 4
        for (int kb = 0; kb < 16; kb++) {
            float4 w0 = wv[(kb * 2 + 0) * 256];
            float4 w1 = wv[(kb * 2 + 1) * 256];
            float w0a[4] = {w0.x, w0.y, w0.z, w0.w};
            float w1a[4] = {w1.x, w1.y, w1.z, w1.w};
#pragma unroll
            for (int i = 0; i < 4; i++) {
                ulonglong2 ha = hv[(kb * 4 + i) * 2 + 0];
                ulonglong2 hb = hv[(kb * 4 + i) * 2 + 1];
                ull p0 = pack2(w0a[i]), p1 = pack2(w1a[i]);
                ffma2(acc[0], ha.x, p0); ffma2(acc[1], ha.y, p0);
                ffma2(acc[2], hb.x, p0); ffma2(acc[3], hb.y, p0);
                ffma2(acc[4], ha.x, p1); ffma2(acc[5], ha.y, p1);
                ffma2(acc[6], hb.x, p1); ffma2(acc[7], hb.y, p1);
            }
        }

        if (kq != 0) {
            ull* pp = sh_part + tid * 9;
#pragma unroll
            for (int i = 0; i < 8; i++) pp[i] = acc[i];
        }
        __syncthreads();

        if (tid < 32) {                               // kq==0 reduces 7 partials
#pragma unroll
            for (int k2 = 1; k2 < 8; k2++) {
                const ull* pp = sh_part + (k2 * 32 + tid) * 9;
#pragma unroll
                for (int i = 0; i < 8; i++) fadd2(acc[i], pp[i]);
            }
            ull* g0 = (ull*)(sh_gate + (2 * tid) * 10);
            ull* g1 = (ull*)(sh_gate + (2 * tid + 1) * 10);
#pragma unroll
            for (int j = 0; j < 4; j++) { g0[j] = acc[j]; g1[j] = acc[4 + j]; }
        }
        __syncthreads();

        if (tid < 128) {                              // epilogue: one (b, j) per thread
            const float* gr = sh_gate + (4 * jl) * 10 + b8;
            float pi = gr[0]  + gxv.x;
            float pf = gr[10] + gxv.y;
            float pg = gr[20] + gxv.z;
            float po = gr[30] + gxv.w;
            float ig = sigf(pi), fg = sigf(pf), og = sigf(po);
            float gg = tanh_fast(pg);
            c_val = fg * c_val + ig * gg;
            float h_new = og * tanh_fast(c_val);
            hT0[((t + 1) & 1) * (8 * H_SZ) + (c * 16 + jl) * 8 + b8] = h_new;
            out[(size_t)t * BH + (size_t)(grp * 8 + b8) * H_SZ + c * 16 + jl] = h_new;
            if (t == T_STEPS - 1 && out_size >= TBH + 2 * BH) {
                out[TBH + (grp * 8 + b8) * H_SZ + c * 16 + jl]      = h_new;  // h_f
                out[TBH + BH + (grp * 8 + b8) * H_SZ + c * 16 + jl] = c_val;  // c_f
            }
        }

        // ---- group barrier: monotonic count + release/acquire gen, pure spin ----
        __syncthreads();
        if (tid == 0) {
            __threadfence();
            unsigned arrived = atomicAdd(cnt, 1u) + 1u;
            if (arrived == (unsigned)(t + 1) * (unsigned)NC) {
                st_rel(gen, (unsigned)(t + 1));
            } else {
                while (ld_acq(gen) < (unsigned)(t + 1)) {}
            }
        }
        __syncthreads();
    }
}

// ---------------- launch ----------------
extern "C" void kernel_launch(void* const* d_in, const int* in_sizes, int n_in,
                              void* d_out, int out_size) {
    const float* input = (const float*)d_in[0];
    const float* h0    = (const float*)d_in[1];
    const float* c0    = (const float*)d_in[2];
    const float* Wih   = (const float*)d_in[3];
    const float* Whh   = (const float*)d_in[4];
    const float* bih   = (const float*)d_in[5];
    const float* bhh   = (const float*)d_in[6];
    float* out = (float*)d_out;

    prep_kernel<<<G4, 128>>>(Wih, Whh, bih, bhh, h0);

    dim3 grid(G4 / BN, (T_STEPS * B_SZ) / BM);
    gemm_x_kernel<<<grid, 256>>>(input);

    const int scan_smem = (32768 + 4096 + 4608 + 640) * (int)sizeof(float);  // 168448 B
    cudaFuncSetAttribute(scan_kernel, cudaFuncAttributeMaxDynamicSharedMemorySize, scan_smem);
    scan_kernel<<<NG * NC, 256, scan_smem>>>(c0, out, out_size);
}